// round 2
// baseline (speedup 1.0000x reference)
#include <cuda_runtime.h>
#include <math_constants.h>

#define NMAX 50000
#define EMAX 1600000
#define NH 8

// ---- scratch (static device globals; no allocation allowed) ----
__device__ __align__(16) float g_h[NMAX * 64];     // projected features
__device__ float g_esrc[NMAX * NH];
__device__ float g_edst[NMAX * NH];
__device__ __align__(16) float g_xbuf[NMAX * 64];  // inter-layer activations
__device__ int   g_rowoff[NMAX + 1];
__device__ int   g_cursor[NMAX];
__device__ int   g_csrc[EMAX];

// ---------------- CSR construction ----------------
__global__ void zero_counts(int n) {
    int i = blockIdx.x * blockDim.x + threadIdx.x;
    if (i < n) g_cursor[i] = 0;
}

__global__ void count_deg(const int* __restrict__ dst, int e) {
    int i = blockIdx.x * blockDim.x + threadIdx.x;
    if (i < e) atomicAdd(&g_cursor[dst[i]], 1);
}

__global__ void scan_kernel(int n) {
    __shared__ int sums[1024];
    int tid = threadIdx.x;
    int ch = (n + 1023) / 1024;
    int start = tid * ch;
    int local = 0;
    for (int i = 0; i < ch; i++) {
        int idx = start + i;
        if (idx < n) local += g_cursor[idx];
    }
    sums[tid] = local;
    __syncthreads();
    for (int off = 1; off < 1024; off <<= 1) {
        int v = (tid >= off) ? sums[tid - off] : 0;
        __syncthreads();
        sums[tid] += v;
        __syncthreads();
    }
    int run = sums[tid] - local;
    for (int i = 0; i < ch; i++) {
        int idx = start + i;
        if (idx < n) {
            int c = g_cursor[idx];
            g_rowoff[idx] = run;
            g_cursor[idx] = run;
            run += c;
        }
    }
    if (tid == 1023) g_rowoff[n] = sums[1023];
}

__global__ void fill_csr(const int* __restrict__ src, const int* __restrict__ dst, int e) {
    int i = blockIdx.x * blockDim.x + threadIdx.x;
    if (i < e) {
        int pos = atomicAdd(&g_cursor[dst[i]], 1);
        g_csrc[pos] = src[i];
    }
}

// ---------------- tiled GEMM: C[32 x 64] per block, f32x2 packed FMA ----------------
// 128 threads: tx in [0,16) owns cols 4tx..4tx+3, ty in [0,8) owns rows 4ty..4ty+3.
template <int FIN>
__global__ void gemm_tiled(const float* __restrict__ xin,
                           const float* __restrict__ W, int n) {
    __shared__ float sA[32 * FIN];   // [row][k]
    __shared__ float sB[FIN * 64];   // [k][col]
    int tid = threadIdx.x;
    int block_row = blockIdx.x * 32;
    const float* xp = xin ? xin : g_xbuf;

    // load W tile (row-major [FIN][64]) straight into sB
    const float4* W4 = (const float4*)W;
    for (int i = tid; i < FIN * 16; i += 128) ((float4*)sB)[i] = W4[i];

    // load x tile
    for (int i = tid; i < FIN * 8; i += 128) {
        int row = i / (FIN / 4);
        int kk = (i % (FIN / 4)) * 4;
        float4 v = make_float4(0.f, 0.f, 0.f, 0.f);
        int gr = block_row + row;
        if (gr < n) v = *(const float4*)(xp + gr * FIN + kk);
        *(float4*)(sA + row * FIN + kk) = v;
    }
    __syncthreads();

    int tx = tid & 15, ty = tid >> 4;
    unsigned long long acc[4][2];
#pragma unroll
    for (int r = 0; r < 4; r++) { acc[r][0] = 0ull; acc[r][1] = 0ull; }

#pragma unroll 8
    for (int k = 0; k < FIN; k++) {
        unsigned long long b01 = *(const unsigned long long*)&sB[k * 64 + 4 * tx];
        unsigned long long b23 = *(const unsigned long long*)&sB[k * 64 + 4 * tx + 2];
#pragma unroll
        for (int r = 0; r < 4; r++) {
            float a = sA[(4 * ty + r) * FIN + k];
            unsigned long long pa;
            asm("mov.b64 %0, {%1, %1};" : "=l"(pa) : "r"(__float_as_uint(a)));
            asm("fma.rn.f32x2 %0, %1, %2, %0;" : "+l"(acc[r][0]) : "l"(pa), "l"(b01));
            asm("fma.rn.f32x2 %0, %1, %2, %0;" : "+l"(acc[r][1]) : "l"(pa), "l"(b23));
        }
    }

#pragma unroll
    for (int r = 0; r < 4; r++) {
        int row = block_row + 4 * ty + r;
        if (row < n) {
            unsigned long long* out = (unsigned long long*)(g_h + row * 64);
            out[2 * tx]     = acc[r][0];
            out[2 * tx + 1] = acc[r][1];
        }
    }
}

// ---------------- per-(node, head) attention logits ----------------
__global__ void att_logits(const float* __restrict__ att, int n) {
    int idx = blockIdx.x * blockDim.x + threadIdx.x;
    if (idx >= n * NH) return;
    int row = idx >> 3, head = idx & 7;
    const float4* hp = (const float4*)(g_h + row * 64 + head * 8);
    float4 h0 = hp[0], h1 = hp[1];
    const float* a0 = att + head * 8;
    const float* a1 = att + 64 + head * 8;
    float es = h0.x * a0[0] + h0.y * a0[1] + h0.z * a0[2] + h0.w * a0[3]
             + h1.x * a0[4] + h1.y * a0[5] + h1.z * a0[6] + h1.w * a0[7];
    float ev = h0.x * a1[0] + h0.y * a1[1] + h0.z * a1[2] + h0.w * a1[3]
             + h1.x * a1[4] + h1.y * a1[5] + h1.z * a1[6] + h1.w * a1[7];
    g_esrc[idx] = es;
    g_edst[idx] = ev;
}

// ---------------- per-dst online-softmax aggregation, 4-edge batched ----------------
__global__ void agg_kernel(const float* __restrict__ bias,
                           float* __restrict__ xout, int apply_elu, int n) {
    int wg = (blockIdx.x * blockDim.x + threadIdx.x) >> 5;
    int lane = threadIdx.x & 31;
    if (wg >= n) return;
    int head = lane >> 2;
    const float* __restrict__ esrc = g_esrc;
    const int* __restrict__ csrc = g_csrc;
    const float2* __restrict__ h2 = (const float2*)g_h;

    float ed = g_edst[wg * NH + head];
    int beg = g_rowoff[wg], end = g_rowoff[wg + 1];

    float m = -CUDART_INF_F, s = 0.f, ax = 0.f, ay = 0.f;
    int i = beg;
    for (; i + 4 <= end; i += 4) {
        int s0 = csrc[i], s1 = csrc[i + 1], s2 = csrc[i + 2], s3 = csrc[i + 3];
        float2 v0 = h2[s0 * 32 + lane];
        float2 v1 = h2[s1 * 32 + lane];
        float2 v2 = h2[s2 * 32 + lane];
        float2 v3 = h2[s3 * 32 + lane];
        float e0 = esrc[s0 * NH + head] + ed;
        float e1 = esrc[s1 * NH + head] + ed;
        float e2 = esrc[s2 * NH + head] + ed;
        float e3 = esrc[s3 * NH + head] + ed;
        e0 = e0 > 0.f ? e0 : 0.2f * e0;
        e1 = e1 > 0.f ? e1 : 0.2f * e1;
        e2 = e2 > 0.f ? e2 : 0.2f * e2;
        e3 = e3 > 0.f ? e3 : 0.2f * e3;
        float mx = fmaxf(fmaxf(e0, e1), fmaxf(e2, e3));
        float nm = fmaxf(m, mx);
        float c = __expf(m - nm);
        float p0 = __expf(e0 - nm);
        float p1 = __expf(e1 - nm);
        float p2 = __expf(e2 - nm);
        float p3 = __expf(e3 - nm);
        s  = s * c  + ((p0 + p1) + (p2 + p3));
        ax = ax * c + ((p0 * v0.x + p1 * v1.x) + (p2 * v2.x + p3 * v3.x));
        ay = ay * c + ((p0 * v0.y + p1 * v1.y) + (p2 * v2.y + p3 * v3.y));
        m = nm;
    }
    for (; i < end; i++) {
        int s0 = csrc[i];
        float2 v0 = h2[s0 * 32 + lane];
        float e0 = esrc[s0 * NH + head] + ed;
        e0 = e0 > 0.f ? e0 : 0.2f * e0;
        float nm = fmaxf(m, e0);
        float c = __expf(m - nm);
        float p0 = __expf(e0 - nm);
        s  = s * c  + p0;
        ax = ax * c + p0 * v0.x;
        ay = ay * c + p0 * v0.y;
        m = nm;
    }
    float inv = 1.f / (s + 1e-16f);
    float o0 = ax * inv + bias[2 * lane];
    float o1 = ay * inv + bias[2 * lane + 1];
    if (apply_elu) {
        o0 = o0 > 0.f ? o0 : expm1f(o0);
        o1 = o1 > 0.f ? o1 : expm1f(o1);
    }
    float* dest = xout ? xout : g_xbuf;
    ((float2*)dest)[wg * 32 + lane] = make_float2(o0, o1);
}

// ---------------- launch ----------------
extern "C" void kernel_launch(void* const* d_in, const int* in_sizes, int n_in,
                              void* d_out, int out_size) {
    const float* x  = (const float*)d_in[0];
    const int*   ei = (const int*)d_in[1];
    int n = in_sizes[0] / 128;
    int e = in_sizes[1] / 2;
    const int* src = ei;
    const int* dst = ei + e;

    const float* W[4], *att[4], *b[4];
    for (int l = 0; l < 4; l++) {
        W[l]   = (const float*)d_in[2 + 3 * l];
        att[l] = (const float*)d_in[3 + 3 * l];
        b[l]   = (const float*)d_in[4 + 3 * l];
    }

    // CSR build
    zero_counts<<<(n + 255) / 256, 256>>>(n);
    count_deg<<<(e + 255) / 256, 256>>>(dst, e);
    scan_kernel<<<1, 1024>>>(n);
    fill_csr<<<(e + 255) / 256, 256>>>(src, dst, e);

    int gemm_blk = (n + 31) / 32;
    int log_blk  = (n * NH + 255) / 256;
    int agg_blk  = (n + 7) / 8;

    gemm_tiled<128><<<gemm_blk, 128>>>(x, W[0], n);
    att_logits<<<log_blk, 256>>>(att[0], n);
    agg_kernel<<<agg_blk, 256>>>(b[0], nullptr, 1, n);

    gemm_tiled<64><<<gemm_blk, 128>>>(nullptr, W[1], n);
    att_logits<<<log_blk, 256>>>(att[1], n);
    agg_kernel<<<agg_blk, 256>>>(b[1], nullptr, 1, n);

    gemm_tiled<64><<<gemm_blk, 128>>>(nullptr, W[2], n);
    att_logits<<<log_blk, 256>>>(att[2], n);
    agg_kernel<<<agg_blk, 256>>>(b[2], nullptr, 1, n);

    gemm_tiled<64><<<gemm_blk, 128>>>(nullptr, W[3], n);
    att_logits<<<log_blk, 256>>>(att[3], n);
    agg_kernel<<<agg_blk, 256>>>(b[3], (float*)d_out, 0, n);
}

// round 3
// speedup vs baseline: 1.2197x; 1.2197x over previous
#include <cuda_runtime.h>
#include <cuda_fp16.h>
#include <math_constants.h>

#define NMAX 50000
#define EMAX 1600000
#define HD 64
#define NH 8

// ---- scratch (static device globals; no allocation allowed) ----
__device__ __align__(16) __half g_hh[NMAX * HD];   // fp16 projected features (gather copy)
__device__ float g_esrc[NMAX * NH];
__device__ float g_edst[NMAX * NH];
__device__ __align__(16) float g_xbuf[NMAX * HD];  // inter-layer activations (fp32)
__device__ int   g_rowoff[NMAX + 1];
__device__ int   g_cursor[NMAX];
__device__ int   g_csrc[EMAX];

// ---------------- CSR construction ----------------
__global__ void zero_counts(int n) {
    int i = blockIdx.x * blockDim.x + threadIdx.x;
    if (i < n) g_cursor[i] = 0;
}

__global__ void count_deg(const int* __restrict__ dst, int e) {
    int i = blockIdx.x * blockDim.x + threadIdx.x;
    if (i < e) atomicAdd(&g_cursor[dst[i]], 1);
}

__global__ void scan_kernel(int n) {
    __shared__ int sums[1024];
    int tid = threadIdx.x;
    int ch = (n + 1023) / 1024;
    int start = tid * ch;
    int local = 0;
    for (int i = 0; i < ch; i++) {
        int idx = start + i;
        if (idx < n) local += g_cursor[idx];
    }
    sums[tid] = local;
    __syncthreads();
    for (int off = 1; off < 1024; off <<= 1) {
        int v = (tid >= off) ? sums[tid - off] : 0;
        __syncthreads();
        sums[tid] += v;
        __syncthreads();
    }
    int run = sums[tid] - local;
    for (int i = 0; i < ch; i++) {
        int idx = start + i;
        if (idx < n) {
            int c = g_cursor[idx];
            g_rowoff[idx] = run;
            g_cursor[idx] = run;
            run += c;
        }
    }
    if (tid == 1023) g_rowoff[n] = sums[1023];
}

__global__ void fill_csr(const int* __restrict__ src, const int* __restrict__ dst, int e) {
    int i = blockIdx.x * blockDim.x + threadIdx.x;
    if (i < e) {
        int pos = atomicAdd(&g_cursor[dst[i]], 1);
        g_csrc[pos] = src[i];
    }
}

// ---------------- fused GEMM + attention logits (R1 structure) ----------------
// One warp per node row. Lane owns output cols (2*lane, 2*lane+1).
template <int FIN>
__global__ void gemm_att(const float* __restrict__ xin,
                         const float* __restrict__ W,
                         const float* __restrict__ att, int n) {
    __shared__ float2 sW[FIN * 32];
    __shared__ float  sx[8][FIN];
    int tid = threadIdx.x;
    const float2* W2 = (const float2*)W;
    for (int i = tid; i < FIN * 32; i += 256) sW[i] = W2[i];

    int warp = tid >> 5, lane = tid & 31;
    int row = blockIdx.x * 8 + warp;
    const float* xp = xin ? xin : g_xbuf;
    if (row < n)
        for (int k = lane; k < FIN; k += 32) sx[warp][k] = xp[row * FIN + k];
    __syncthreads();
    if (row >= n) return;

    float a0 = 0.f, a1 = 0.f;
#pragma unroll
    for (int k = 0; k < FIN; k++) {
        float xv = sx[warp][k];
        float2 w = sW[k * 32 + lane];
        a0 = fmaf(xv, w.x, a0);
        a1 = fmaf(xv, w.y, a1);
    }
    // fp16 packed store of the gather copy (halves agg read bytes)
    ((__half2*)g_hh)[row * 32 + lane] = __floats2half2_rn(a0, a1);

    int head = lane >> 2;
    int d = (2 * lane) & 7;
    float p0 = a0 * att[head * 8 + d]      + a1 * att[head * 8 + d + 1];
    float p1 = a0 * att[64 + head * 8 + d] + a1 * att[64 + head * 8 + d + 1];
    p0 += __shfl_xor_sync(0xffffffffu, p0, 1);
    p0 += __shfl_xor_sync(0xffffffffu, p0, 2);
    p1 += __shfl_xor_sync(0xffffffffu, p1, 1);
    p1 += __shfl_xor_sync(0xffffffffu, p1, 2);
    if ((lane & 3) == 0) {
        g_esrc[row * NH + head] = p0;
        g_edst[row * NH + head] = p1;
    }
}

// ---------------- per-dst online-softmax aggregation (fp16 gather) ----------------
__global__ void agg_kernel(const float* __restrict__ bias,
                           float* __restrict__ xout, int apply_elu, int n) {
    int wg = (blockIdx.x * blockDim.x + threadIdx.x) >> 5;
    int lane = threadIdx.x & 31;
    if (wg >= n) return;
    int head = lane >> 2;
    float ed = g_edst[wg * NH + head];
    int beg = g_rowoff[wg], end = g_rowoff[wg + 1];
    const __half2* __restrict__ hh = (const __half2*)g_hh;
    const float* __restrict__ esrc = g_esrc;
    const int* __restrict__ csrc = g_csrc;

    float m = -CUDART_INF_F, s = 0.f, ax = 0.f, ay = 0.f;
    for (int i = beg; i < end; i++) {
        int srcn = csrc[i];
        float es = esrc[srcn * NH + head];
        float v = es + ed;
        float e = v > 0.f ? v : 0.2f * v;        // leaky relu
        float2 hv = __half22float2(hh[srcn * 32 + lane]);
        float nm = fmaxf(m, e);
        float c = __expf(m - nm);                // exp(-inf)=0 handles first edge
        float p = __expf(e - nm);
        s  = s  * c + p;
        ax = ax * c + p * hv.x;
        ay = ay * c + p * hv.y;
        m = nm;
    }
    float inv = 1.f / (s + 1e-16f);
    float o0 = ax * inv + bias[2 * lane];
    float o1 = ay * inv + bias[2 * lane + 1];
    if (apply_elu) {
        o0 = o0 > 0.f ? o0 : expm1f(o0);
        o1 = o1 > 0.f ? o1 : expm1f(o1);
    }
    float* dest = xout ? xout : g_xbuf;
    ((float2*)dest)[wg * 32 + lane] = make_float2(o0, o1);
}

// ---------------- launch ----------------
extern "C" void kernel_launch(void* const* d_in, const int* in_sizes, int n_in,
                              void* d_out, int out_size) {
    const float* x  = (const float*)d_in[0];
    const int*   ei = (const int*)d_in[1];
    int n = in_sizes[0] / 128;
    int e = in_sizes[1] / 2;
    const int* src = ei;
    const int* dst = ei + e;

    const float* W[4], *att[4], *b[4];
    for (int l = 0; l < 4; l++) {
        W[l]   = (const float*)d_in[2 + 3 * l];
        att[l] = (const float*)d_in[3 + 3 * l];
        b[l]   = (const float*)d_in[4 + 3 * l];
    }

    // CSR build
    zero_counts<<<(n + 255) / 256, 256>>>(n);
    count_deg<<<(e + 255) / 256, 256>>>(dst, e);
    scan_kernel<<<1, 1024>>>(n);
    fill_csr<<<(e + 255) / 256, 256>>>(src, dst, e);

    int gblk = (n + 7) / 8;

    gemm_att<128><<<gblk, 256>>>(x, W[0], att[0], n);
    agg_kernel<<<gblk, 256>>>(b[0], nullptr, 1, n);
    gemm_att<64><<<gblk, 256>>>(nullptr, W[1], att[1], n);
    agg_kernel<<<gblk, 256>>>(b[1], nullptr, 1, n);
    gemm_att<64><<<gblk, 256>>>(nullptr, W[2], att[2], n);
    agg_kernel<<<gblk, 256>>>(b[2], nullptr, 1, n);
    gemm_att<64><<<gblk, 256>>>(nullptr, W[3], att[3], n);
    agg_kernel<<<gblk, 256>>>(b[3], (float*)d_out, 0, n);
}

// round 4
// speedup vs baseline: 1.3392x; 1.0980x over previous
#include <cuda_runtime.h>
#include <cuda_fp16.h>
#include <math_constants.h>

#define NMAX 50000
#define EMAX 1600000
#define HD 64
#define NH 8

// ---- scratch (static device globals; no allocation allowed) ----
__device__ __align__(16) __half g_hh[NMAX * HD];   // fp16 projected features (gather copy)
__device__ float g_esrc[NMAX * NH];
__device__ float g_edst[NMAX * NH];
__device__ __align__(16) float g_xbuf[NMAX * HD];  // inter-layer activations (fp32)
__device__ int   g_rowoff[NMAX + 1];
__device__ int   g_cursor[NMAX];
__device__ int   g_csrc[EMAX];

// ---------------- CSR construction ----------------
__global__ void zero_counts(int n) {
    int i = blockIdx.x * blockDim.x + threadIdx.x;
    if (i < n) g_cursor[i] = 0;
}

__global__ void count_deg(const int* __restrict__ dst, int e) {
    int i = blockIdx.x * blockDim.x + threadIdx.x;
    if (i < e) atomicAdd(&g_cursor[dst[i]], 1);
}

__global__ void scan_kernel(int n) {
    __shared__ int sums[1024];
    int tid = threadIdx.x;
    int ch = (n + 1023) / 1024;
    int start = tid * ch;
    int local = 0;
    for (int i = 0; i < ch; i++) {
        int idx = start + i;
        if (idx < n) local += g_cursor[idx];
    }
    sums[tid] = local;
    __syncthreads();
    for (int off = 1; off < 1024; off <<= 1) {
        int v = (tid >= off) ? sums[tid - off] : 0;
        __syncthreads();
        sums[tid] += v;
        __syncthreads();
    }
    int run = sums[tid] - local;
    for (int i = 0; i < ch; i++) {
        int idx = start + i;
        if (idx < n) {
            int c = g_cursor[idx];
            g_rowoff[idx] = run;
            g_cursor[idx] = run;
            run += c;
        }
    }
    if (tid == 1023) g_rowoff[n] = sums[1023];
}

__global__ void fill_csr(const int* __restrict__ src, const int* __restrict__ dst, int e) {
    int i = blockIdx.x * blockDim.x + threadIdx.x;
    if (i < e) {
        int pos = atomicAdd(&g_cursor[dst[i]], 1);
        g_csrc[pos] = src[i];
    }
}

// ---------------- fused GEMM + attention logits ----------------
// One warp per node row. Lane owns output cols (2*lane, 2*lane+1).
template <int FIN>
__global__ void gemm_att(const float* __restrict__ xin,
                         const float* __restrict__ W,
                         const float* __restrict__ att, int n) {
    __shared__ float2 sW[FIN * 32];
    __shared__ float  sx[8][FIN];
    int tid = threadIdx.x;
    const float2* W2 = (const float2*)W;
    for (int i = tid; i < FIN * 32; i += 256) sW[i] = W2[i];

    int warp = tid >> 5, lane = tid & 31;
    int row = blockIdx.x * 8 + warp;
    const float* xp = xin ? xin : g_xbuf;
    if (row < n)
        for (int k = lane; k < FIN; k += 32) sx[warp][k] = xp[row * FIN + k];
    __syncthreads();
    if (row >= n) return;

    float a0 = 0.f, a1 = 0.f;
#pragma unroll
    for (int k = 0; k < FIN; k++) {
        float xv = sx[warp][k];
        float2 w = sW[k * 32 + lane];
        a0 = fmaf(xv, w.x, a0);
        a1 = fmaf(xv, w.y, a1);
    }
    ((__half2*)g_hh)[row * 32 + lane] = __floats2half2_rn(a0, a1);

    int head = lane >> 2;
    int d = (2 * lane) & 7;
    float p0 = a0 * att[head * 8 + d]      + a1 * att[head * 8 + d + 1];
    float p1 = a0 * att[64 + head * 8 + d] + a1 * att[64 + head * 8 + d + 1];
    p0 += __shfl_xor_sync(0xffffffffu, p0, 1);
    p0 += __shfl_xor_sync(0xffffffffu, p0, 2);
    p1 += __shfl_xor_sync(0xffffffffu, p1, 1);
    p1 += __shfl_xor_sync(0xffffffffu, p1, 2);
    if ((lane & 3) == 0) {
        g_esrc[row * NH + head] = p0;
        g_edst[row * NH + head] = p1;
    }
}

// ---------------- per-dst online-softmax aggregation, 8-edge batched ----------------
__global__ void agg_kernel(const float* __restrict__ bias,
                           float* __restrict__ xout, int apply_elu, int n) {
    int wg = (blockIdx.x * blockDim.x + threadIdx.x) >> 5;
    int lane = threadIdx.x & 31;
    if (wg >= n) return;
    int head = lane >> 2;
    float ed = g_edst[wg * NH + head];
    int beg = g_rowoff[wg], end = g_rowoff[wg + 1];
    const __half2* __restrict__ hh = (const __half2*)g_hh;
    const float* __restrict__ esrc = g_esrc;
    const int* __restrict__ csrc = g_csrc;

    float m = -CUDART_INF_F, s = 0.f, ax = 0.f, ay = 0.f;
    int i = beg;
    for (; i + 8 <= end; i += 8) {
        // 8 independent index loads, then 16 independent gathers (MLP ~16)
        int idx[8];
#pragma unroll
        for (int j = 0; j < 8; j++) idx[j] = csrc[i + j];
        float ev[8];
        __half2 hv[8];
#pragma unroll
        for (int j = 0; j < 8; j++) ev[j] = esrc[idx[j] * NH + head];
#pragma unroll
        for (int j = 0; j < 8; j++) hv[j] = hh[idx[j] * 32 + lane];

        float mx = -CUDART_INF_F;
#pragma unroll
        for (int j = 0; j < 8; j++) {
            float v = ev[j] + ed;
            ev[j] = v > 0.f ? v : 0.2f * v;      // leaky relu
            mx = fmaxf(mx, ev[j]);
        }
        float nm = fmaxf(m, mx);
        float c = __expf(m - nm);                // one rescale per 8 edges
        s *= c; ax *= c; ay *= c;
#pragma unroll
        for (int j = 0; j < 8; j++) {
            float p = __expf(ev[j] - nm);
            float2 v = __half22float2(hv[j]);
            s  += p;
            ax = fmaf(p, v.x, ax);
            ay = fmaf(p, v.y, ay);
        }
        m = nm;
    }
    for (; i < end; i++) {
        int srcn = csrc[i];
        float es = esrc[srcn * NH + head];
        float v = es + ed;
        float e = v > 0.f ? v : 0.2f * v;
        float2 hv = __half22float2(hh[srcn * 32 + lane]);
        float nm = fmaxf(m, e);
        float c = __expf(m - nm);
        float p = __expf(e - nm);
        s  = s  * c + p;
        ax = ax * c + p * hv.x;
        ay = ay * c + p * hv.y;
        m = nm;
    }
    float inv = 1.f / (s + 1e-16f);
    float o0 = ax * inv + bias[2 * lane];
    float o1 = ay * inv + bias[2 * lane + 1];
    if (apply_elu) {
        o0 = o0 > 0.f ? o0 : expm1f(o0);
        o1 = o1 > 0.f ? o1 : expm1f(o1);
    }
    float* dest = xout ? xout : g_xbuf;
    ((float2*)dest)[wg * 32 + lane] = make_float2(o0, o1);
}

// ---------------- launch ----------------
extern "C" void kernel_launch(void* const* d_in, const int* in_sizes, int n_in,
                              void* d_out, int out_size) {
    const float* x  = (const float*)d_in[0];
    const int*   ei = (const int*)d_in[1];
    int n = in_sizes[0] / 128;
    int e = in_sizes[1] / 2;
    const int* src = ei;
    const int* dst = ei + e;

    const float* W[4], *att[4], *b[4];
    for (int l = 0; l < 4; l++) {
        W[l]   = (const float*)d_in[2 + 3 * l];
        att[l] = (const float*)d_in[3 + 3 * l];
        b[l]   = (const float*)d_in[4 + 3 * l];
    }

    // CSR build
    zero_counts<<<(n + 255) / 256, 256>>>(n);
    count_deg<<<(e + 255) / 256, 256>>>(dst, e);
    scan_kernel<<<1, 1024>>>(n);
    fill_csr<<<(e + 255) / 256, 256>>>(src, dst, e);

    int gblk = (n + 7) / 8;

    gemm_att<128><<<gblk, 256>>>(x, W[0], att[0], n);
    agg_kernel<<<gblk, 256>>>(b[0], nullptr, 1, n);
    gemm_att<64><<<gblk, 256>>>(nullptr, W[1], att[1], n);
    agg_kernel<<<gblk, 256>>>(b[1], nullptr, 1, n);
    gemm_att<64><<<gblk, 256>>>(nullptr, W[2], att[2], n);
    agg_kernel<<<gblk, 256>>>(b[2], nullptr, 1, n);
    gemm_att<64><<<gblk, 256>>>(nullptr, W[3], att[3], n);
    agg_kernel<<<gblk, 256>>>(b[3], (float*)d_out, 0, n);
}

// round 5
// speedup vs baseline: 1.5355x; 1.1465x over previous
#include <cuda_runtime.h>
#include <cuda_fp16.h>
#include <math_constants.h>

#define NMAX 50000
#define EMAX 1600000
#define HD 64
#define NH 8

// ---- scratch (static device globals; no allocation allowed) ----
__device__ __align__(16) __half g_hh[NMAX * HD];   // fp16 projected features (gather copy)
__device__ float g_esrc[NMAX * NH];
__device__ float g_edst[NMAX * NH];
__device__ __align__(16) float g_xbuf[NMAX * HD];  // inter-layer activations (fp32)
__device__ int   g_rowoff[NMAX + 1];
__device__ int   g_cursor[NMAX];
__device__ int   g_csrc[EMAX];

// ---------------- CSR construction ----------------
__global__ void zero_counts(int n) {
    int i = blockIdx.x * blockDim.x + threadIdx.x;
    if (i < n) g_cursor[i] = 0;
}

__global__ void count_deg(const int* __restrict__ dst, int e) {
    int i = blockIdx.x * blockDim.x + threadIdx.x;
    if (i < e) atomicAdd(&g_cursor[dst[i]], 1);
}

__global__ void scan_kernel(int n) {
    __shared__ int sums[1024];
    int tid = threadIdx.x;
    int ch = (n + 1023) / 1024;
    int start = tid * ch;
    int local = 0;
    for (int i = 0; i < ch; i++) {
        int idx = start + i;
        if (idx < n) local += g_cursor[idx];
    }
    sums[tid] = local;
    __syncthreads();
    for (int off = 1; off < 1024; off <<= 1) {
        int v = (tid >= off) ? sums[tid - off] : 0;
        __syncthreads();
        sums[tid] += v;
        __syncthreads();
    }
    int run = sums[tid] - local;
    for (int i = 0; i < ch; i++) {
        int idx = start + i;
        if (idx < n) {
            int c = g_cursor[idx];
            g_rowoff[idx] = run;
            g_cursor[idx] = run;
            run += c;
        }
    }
    if (tid == 1023) g_rowoff[n] = sums[1023];
}

__global__ void fill_csr(const int* __restrict__ src, const int* __restrict__ dst, int e) {
    int i = blockIdx.x * blockDim.x + threadIdx.x;
    if (i < e) {
        int pos = atomicAdd(&g_cursor[dst[i]], 1);
        g_csrc[pos] = src[i];
    }
}

// ---------------- fused GEMM + attention logits ----------------
// 8 warps/block, 4 rows per warp (32 rows/block). Lane owns cols (2l, 2l+1).
// f32x2 packed FMA: each sW LDS.64 feeds 4 FFMA2 (8 MACs).
template <int FIN>
__global__ void gemm_att(const float* __restrict__ xin,
                         const float* __restrict__ W,
                         const float* __restrict__ att, int n) {
    __shared__ float2 sW[FIN * 32];
    __shared__ float  sx[32][FIN];
    int tid = threadIdx.x;
    const float2* W2 = (const float2*)W;
    for (int i = tid; i < FIN * 32; i += 256) sW[i] = W2[i];

    int row0 = blockIdx.x * 32;
    const float* xp = xin ? xin : g_xbuf;
    for (int i = tid; i < 8 * FIN; i += 256) {      // 32 rows * FIN/4 float4s
        int r = i / (FIN / 4);
        int kk = (i % (FIN / 4)) * 4;
        float4 v = make_float4(0.f, 0.f, 0.f, 0.f);
        if (row0 + r < n) v = *(const float4*)(xp + (row0 + r) * FIN + kk);
        *(float4*)(&sx[r][kk]) = v;
    }
    __syncthreads();

    int warp = tid >> 5, lane = tid & 31;
    int r0 = warp * 4;
    const unsigned long long* sW64 = (const unsigned long long*)sW;

    unsigned long long acc[4] = {0ull, 0ull, 0ull, 0ull};
#pragma unroll 8
    for (int k = 0; k < FIN; k++) {
        unsigned long long wp = sW64[k * 32 + lane];
#pragma unroll
        for (int r = 0; r < 4; r++) {
            float a = sx[r0 + r][k];                 // warp broadcast
            unsigned long long pa;
            asm("mov.b64 %0, {%1, %1};" : "=l"(pa) : "r"(__float_as_uint(a)));
            asm("fma.rn.f32x2 %0, %1, %2, %0;" : "+l"(acc[r]) : "l"(pa), "l"(wp));
        }
    }

    int head = lane >> 2;
    int d = (2 * lane) & 7;
#pragma unroll
    for (int r = 0; r < 4; r++) {
        int row = row0 + r0 + r;
        float a0, a1;
        asm("mov.b64 {%0, %1}, %2;" : "=f"(a0), "=f"(a1) : "l"(acc[r]));
        float p0 = a0 * att[head * 8 + d]      + a1 * att[head * 8 + d + 1];
        float p1 = a0 * att[64 + head * 8 + d] + a1 * att[64 + head * 8 + d + 1];
        p0 += __shfl_xor_sync(0xffffffffu, p0, 1);
        p0 += __shfl_xor_sync(0xffffffffu, p0, 2);
        p1 += __shfl_xor_sync(0xffffffffu, p1, 1);
        p1 += __shfl_xor_sync(0xffffffffu, p1, 2);
        if (row < n) {
            ((__half2*)g_hh)[row * 32 + lane] = __floats2half2_rn(a0, a1);
            if ((lane & 3) == 0) {
                g_esrc[row * NH + head] = p0;
                g_edst[row * NH + head] = p1;
            }
        }
    }
}

// ---------------- per-dst online-softmax aggregation, 8-batched + idx prefetch ----------------
__global__ void agg_kernel(const float* __restrict__ bias,
                           float* __restrict__ xout, int apply_elu, int n) {
    int wg = (blockIdx.x * blockDim.x + threadIdx.x) >> 5;
    int lane = threadIdx.x & 31;
    if (wg >= n) return;
    int head = lane >> 2;
    float ed = g_edst[wg * NH + head];
    int beg = g_rowoff[wg], end = g_rowoff[wg + 1];
    const __half2* __restrict__ hh = (const __half2*)g_hh;
    const float* __restrict__ esrc = g_esrc;
    const int* __restrict__ csrc = g_csrc;

    float m = -CUDART_INF_F, s = 0.f, ax = 0.f, ay = 0.f;
    int nb = (end - beg) >> 3;           // full 8-edge batches
    int idxA[8];
    if (nb > 0) {
#pragma unroll
        for (int j = 0; j < 8; j++) idxA[j] = csrc[beg + j];
    }
    for (int b = 0; b < nb; b++) {
        int base = beg + (b << 3);
        int idxB[8];
        if (b + 1 < nb) {                // prefetch next batch's indices
#pragma unroll
            for (int j = 0; j < 8; j++) idxB[j] = csrc[base + 8 + j];
        }
        float ev[8];
        __half2 hv[8];
#pragma unroll
        for (int j = 0; j < 8; j++) ev[j] = esrc[idxA[j] * NH + head];
#pragma unroll
        for (int j = 0; j < 8; j++) hv[j] = hh[idxA[j] * 32 + lane];

        float mx = -CUDART_INF_F;
#pragma unroll
        for (int j = 0; j < 8; j++) {
            float v = ev[j] + ed;
            ev[j] = v > 0.f ? v : 0.2f * v;      // leaky relu
            mx = fmaxf(mx, ev[j]);
        }
        float nm = fmaxf(m, mx);
        float c = __expf(m - nm);                // one rescale per 8 edges
        s *= c; ax *= c; ay *= c;
#pragma unroll
        for (int j = 0; j < 8; j++) {
            float p = __expf(ev[j] - nm);
            float2 v = __half22float2(hv[j]);
            s  += p;
            ax = fmaf(p, v.x, ax);
            ay = fmaf(p, v.y, ay);
        }
        m = nm;
        if (b + 1 < nb) {
#pragma unroll
            for (int j = 0; j < 8; j++) idxA[j] = idxB[j];
        }
    }
    for (int i = beg + (nb << 3); i < end; i++) {
        int srcn = csrc[i];
        float es = esrc[srcn * NH + head];
        float v = es + ed;
        float e = v > 0.f ? v : 0.2f * v;
        float2 hv = __half22float2(hh[srcn * 32 + lane]);
        float nm = fmaxf(m, e);
        float c = __expf(m - nm);
        float p = __expf(e - nm);
        s  = s  * c + p;
        ax = ax * c + p * hv.x;
        ay = ay * c + p * hv.y;
        m = nm;
    }
    float inv = 1.f / (s + 1e-16f);
    float o0 = ax * inv + bias[2 * lane];
    float o1 = ay * inv + bias[2 * lane + 1];
    if (apply_elu) {
        o0 = o0 > 0.f ? o0 : expm1f(o0);
        o1 = o1 > 0.f ? o1 : expm1f(o1);
    }
    float* dest = xout ? xout : g_xbuf;
    ((float2*)dest)[wg * 32 + lane] = make_float2(o0, o1);
}

// ---------------- launch ----------------
extern "C" void kernel_launch(void* const* d_in, const int* in_sizes, int n_in,
                              void* d_out, int out_size) {
    const float* x  = (const float*)d_in[0];
    const int*   ei = (const int*)d_in[1];
    int n = in_sizes[0] / 128;
    int e = in_sizes[1] / 2;
    const int* src = ei;
    const int* dst = ei + e;

    const float* W[4], *att[4], *b[4];
    for (int l = 0; l < 4; l++) {
        W[l]   = (const float*)d_in[2 + 3 * l];
        att[l] = (const float*)d_in[3 + 3 * l];
        b[l]   = (const float*)d_in[4 + 3 * l];
    }

    // CSR build
    zero_counts<<<(n + 255) / 256, 256>>>(n);
    count_deg<<<(e + 255) / 256, 256>>>(dst, e);
    scan_kernel<<<1, 1024>>>(n);
    fill_csr<<<(e + 255) / 256, 256>>>(src, dst, e);

    int gemm_blk = (n + 31) / 32;
    int agg_blk  = (n + 7) / 8;

    gemm_att<128><<<gemm_blk, 256>>>(x, W[0], att[0], n);
    agg_kernel<<<agg_blk, 256>>>(b[0], nullptr, 1, n);
    gemm_att<64><<<gemm_blk, 256>>>(nullptr, W[1], att[1], n);
    agg_kernel<<<agg_blk, 256>>>(b[1], nullptr, 1, n);
    gemm_att<64><<<gemm_blk, 256>>>(nullptr, W[2], att[2], n);
    agg_kernel<<<agg_blk, 256>>>(b[2], nullptr, 1, n);
    gemm_att<64><<<gemm_blk, 256>>>(nullptr, W[3], att[3], n);
    agg_kernel<<<agg_blk, 256>>>(b[3], (float*)d_out, 0, n);
}